// round 14
// baseline (speedup 1.0000x reference)
#include <cuda_runtime.h>
#include <cuda_fp16.h>
#include <math.h>
#include <stdint.h>

#define NRAYS 4096
#define NSAMP 256
#define NTOT  (NRAYS*NSAMP)
#define STRIDE (NTOT + 128)
#define RES   128
#define RES3  (RES*RES*RES)
#define T0    0.2f
#define DT    (2.8f/255.0f)
#define ACT_SHIFT (-4.595119850134589f)

// ---------------- scratch ----------------------------------------------------
__device__ float    g_alpha[NTOT];
__device__ float    g_rgb[3*NTOT];
__device__ float    g_nrm[3*NTOT];
__device__ uint4    g_lat4[2*RES3];     // 16 fp16 latent channels per voxel
__device__ uint2    g_nrm2[RES3];       // nx,ny,nz fp16 + pad
__device__ uint4    g_featr[STRIDE*8];  // row-major: 64 fp16 features per sample
__device__ int      g_sidx[STRIDE];
__device__ int      g_count;

// ---------------- helpers ----------------------------------------------------
__device__ __forceinline__ uint32_t pack16(unsigned short lo, unsigned short hi){
    return (uint32_t)lo | ((uint32_t)hi << 16);
}
__device__ __forceinline__ unsigned short f2h(float v){
    return __half_as_ushort(__float2half_rn(v));
}
__device__ __forceinline__ uint32_t packh2(float a, float b){
    __half2 h = __floats2half2_rn(a, b);
    return *(uint32_t*)&h;
}
__device__ __forceinline__ float2 h2f(uint32_t u){
    __half2 h = *reinterpret_cast<__half2*>(&u);
    return __half22float2(h);
}
__device__ __forceinline__ void mma_fp16(float* d, uint32_t a0, uint32_t a1,
                                         uint32_t a2, uint32_t a3,
                                         uint32_t b0, uint32_t b1){
    asm volatile(
        "mma.sync.aligned.m16n8k16.row.col.f32.f16.f16.f32 "
        "{%0,%1,%2,%3}, {%4,%5,%6,%7}, {%8,%9}, {%0,%1,%2,%3};"
        : "+f"(d[0]), "+f"(d[1]), "+f"(d[2]), "+f"(d[3])
        : "r"(a0), "r"(a1), "r"(a2), "r"(a3), "r"(b0), "r"(b1));
}
__device__ __forceinline__ void mma_fp16h(uint32_t* d, uint32_t a0, uint32_t a1,
                                          uint32_t a2, uint32_t a3,
                                          uint32_t b0, uint32_t b1){
    asm volatile(
        "mma.sync.aligned.m16n8k16.row.col.f16.f16.f16.f16 "
        "{%0,%1}, {%2,%3,%4,%5}, {%6,%7}, {%0,%1};"
        : "+r"(d[0]), "+r"(d[1])
        : "r"(a0), "r"(a1), "r"(a2), "r"(a3), "r"(b0), "r"(b1));
}

// ---------------- kernel 0: grid transpose (2 voxels/thread, float2 reads) ---
__global__ __launch_bounds__(256) void k_xpose(
    const float* __restrict__ lat, const float* __restrict__ nrm)
{
    int v2 = blockIdx.x * 256 + threadIdx.x;
    unsigned short ha[16], hb[16];
    #pragma unroll
    for (int c = 0; c < 16; c++){
        float2 f = __ldg((const float2*)(lat + c*RES3) + v2);
        ha[c] = f2h(f.x); hb[c] = f2h(f.y);
    }
    uint4 w0, w1, w2, w3;
    w0.x = pack16(ha[0],ha[1]);   w0.y = pack16(ha[2],ha[3]);
    w0.z = pack16(ha[4],ha[5]);   w0.w = pack16(ha[6],ha[7]);
    w1.x = pack16(ha[8],ha[9]);   w1.y = pack16(ha[10],ha[11]);
    w1.z = pack16(ha[12],ha[13]); w1.w = pack16(ha[14],ha[15]);
    w2.x = pack16(hb[0],hb[1]);   w2.y = pack16(hb[2],hb[3]);
    w2.z = pack16(hb[4],hb[5]);   w2.w = pack16(hb[6],hb[7]);
    w3.x = pack16(hb[8],hb[9]);   w3.y = pack16(hb[10],hb[11]);
    w3.z = pack16(hb[12],hb[13]); w3.w = pack16(hb[14],hb[15]);
    g_lat4[4*v2]   = w0;
    g_lat4[4*v2+1] = w1;
    g_lat4[4*v2+2] = w2;
    g_lat4[4*v2+3] = w3;
    float2 n0 = __ldg((const float2*)(nrm)            + v2);
    float2 n1 = __ldg((const float2*)(nrm +   RES3)   + v2);
    float2 n2 = __ldg((const float2*)(nrm + 2*RES3)   + v2);
    uint4 nq;
    nq.x = pack16(f2h(n0.x), f2h(n1.x));
    nq.y = pack16(f2h(n2.x), 0);
    nq.z = pack16(f2h(n0.y), f2h(n1.y));
    nq.w = pack16(f2h(n2.y), 0);
    ((uint4*)g_nrm2)[v2] = nq;
}

// ---------------- kernel 1: featurize + compact ------------------------------
__global__ __launch_bounds__(128) void k_feat(
    const float* __restrict__ rays_o, const float* __restrict__ rays_d,
    const float* __restrict__ viewdirs)
{
    int idx  = blockIdx.x * 128 + threadIdx.x;
    int r    = idx >> 8, s = idx & 255;
    int lane = threadIdx.x & 31;

    float ox = rays_o[r*3], oy = rays_o[r*3+1], oz = rays_o[r*3+2];
    float dx = rays_d[r*3], dy = rays_d[r*3+1], dz = rays_d[r*3+2];
    float dinv = rsqrtf(dx*dx + dy*dy + dz*dz);
    dx *= dinv; dy *= dinv; dz *= dinv;

    float t  = T0 + (float)s * DT;
    float px = ox + dx*t, py = oy + dy*t, pz = oz + dz*t;

    bool inb = (px >= -1.0f) & (px <= 1.0f) & (py >= -1.0f) & (py <= 1.0f)
             & (pz >= -1.0f) & (pz <= 1.0f);

    unsigned mask = __ballot_sync(0xffffffffu, inb);
    int base = 0;
    if (mask){
        if (lane == 0) base = atomicAdd(&g_count, __popc(mask));
        base = __shfl_sync(0xffffffffu, base, 0);
    }
    if (!inb){ g_alpha[idx] = 0.0f; return; }
    int pos = base + __popc(mask & ((1u << lane) - 1u));
    g_sidx[pos] = idx;

    float ux = fminf(fmaxf((px + 1.0f) * 0.5f, 0.0f), 1.0f) * 127.0f;
    float uy = fminf(fmaxf((py + 1.0f) * 0.5f, 0.0f), 1.0f) * 127.0f;
    float uz = fminf(fmaxf((pz + 1.0f) * 0.5f, 0.0f), 1.0f) * 127.0f;
    int x0 = min((int)floorf(ux), 126);
    int y0 = min((int)floorf(uy), 126);
    int z0 = min((int)floorf(uz), 126);
    float fx = ux - (float)x0, fy = uy - (float)y0, fz = uz - (float)z0;
    float gx = 1.0f - fx, gy = 1.0f - fy, gz = 1.0f - fz;

    int o000 = (x0*RES + y0)*RES + z0;
    int offs[8] = { o000, o000+1, o000+RES, o000+RES+1,
                    o000+RES*RES, o000+RES*RES+1, o000+RES*RES+RES, o000+RES*RES+RES+1 };
    float ws[8] = { gx*gy*gz, gx*gy*fz, gx*fy*gz, gx*fy*fz,
                    fx*gy*gz, fx*gy*fz, fx*fy*gz, fx*fy*fz };

    float L[16]; float N3[3];
    #pragma unroll
    for (int c = 0; c < 16; c++) L[c] = 0.0f;
    N3[0] = N3[1] = N3[2] = 0.0f;

    #pragma unroll
    for (int c = 0; c < 8; c++){
        int o = offs[c];
        float w = ws[c];
        uint4 pa = __ldg(&g_lat4[2*o]);
        uint4 pb = __ldg(&g_lat4[2*o+1]);
        uint2 pn = __ldg(&g_nrm2[o]);
        float2 f;
        f = h2f(pa.x); L[0]  += w*f.x; L[1]  += w*f.y;
        f = h2f(pa.y); L[2]  += w*f.x; L[3]  += w*f.y;
        f = h2f(pa.z); L[4]  += w*f.x; L[5]  += w*f.y;
        f = h2f(pa.w); L[6]  += w*f.x; L[7]  += w*f.y;
        f = h2f(pb.x); L[8]  += w*f.x; L[9]  += w*f.y;
        f = h2f(pb.y); L[10] += w*f.x; L[11] += w*f.y;
        f = h2f(pb.z); L[12] += w*f.x; L[13] += w*f.y;
        f = h2f(pb.w); L[14] += w*f.x; L[15] += w*f.y;
        f = h2f(pn.x); N3[0] += w*f.x; N3[1] += w*f.y;
        f = h2f(pn.y); N3[2] += w*f.x;
    }

    float nx = N3[0], ny = N3[1], nz = N3[2];
    float nl = sqrtf(nx*nx + ny*ny + nz*nz);
    float ninv = 1.0f / fmaxf(nl, 1e-12f);
    nx *= ninv; ny *= ninv; nz *= ninv;

    float d0 = L[0] + ACT_SHIFT;
    float sp = fmaxf(d0, 0.0f) + log1pf(__expf(-fabsf(d0)));
    g_alpha[idx] = 1.0f - __expf(-sp * 0.5f);
    g_nrm[idx] = nx; g_nrm[NTOT+idx] = ny; g_nrm[2*NTOT+idx] = nz;

    float vx = viewdirs[r*3], vy = viewdirs[r*3+1], vz = viewdirs[r*3+2];
    float vinv = rsqrtf(vx*vx + vy*vy + vz*vz);
    vx *= vinv; vy *= vinv; vz *= vinv;
    float dot = -(vx*nx + vy*ny + vz*nz);
    float rdx = 2.0f*dot*nx + vx, rdy = 2.0f*dot*ny + vy, rdz = 2.0f*dot*nz + vz;

    float fv[54];
    #pragma unroll
    for (int c = 0; c < 15; c++) fv[c] = L[c+1];
    fv[15] = rdx; fv[16] = rdy; fv[17] = rdz;
    float fq = 1.0f;
    #pragma unroll
    for (int k = 0; k < 6; k++){
        float sx, cx, sy, cy, sz, cz;
        __sincosf(fq*rdx, &sx, &cx);
        __sincosf(fq*rdy, &sy, &cy);
        __sincosf(fq*rdz, &sz, &cz);
        fv[18+3*k] = sx; fv[18+3*k+1] = sy; fv[18+3*k+2] = sz;
        fv[36+3*k] = cx; fv[36+3*k+1] = cy; fv[36+3*k+2] = cz;
        fq *= 2.0f;
    }
    uint32_t fw[32];
    #pragma unroll
    for (int w = 0; w < 27; w++) fw[w] = packh2(fv[2*w], fv[2*w+1]);
    #pragma unroll
    for (int w = 27; w < 32; w++) fw[w] = 0;
    uint4* dst = g_featr + pos*8;
    #pragma unroll
    for (int i = 0; i < 8; i++)
        dst[i] = make_uint4(fw[4*i], fw[4*i+1], fw[4*i+2], fw[4*i+3]);
}

// ---------------- kernel 2: HMMA MLP, 8 warps x 16 rows per 128-row tile -----
#define BF_OFF    0          // B frags: 3*8*4*32*8 = 24576
#define BIASH_OFF 24576      // b0,b1 as half2: 2*128 = 256
#define BIAS2_OFF 24832      // b2 f32: 256
#define W3B_OFF   25088      // 192*4 = 768
#define B3_OFF    25856      // 16
#define SMEM_SZ   25872

__global__ __launch_bounds__(256) void k_mlp(
    const float* __restrict__ W0, const float* __restrict__ b0,
    const float* __restrict__ W1, const float* __restrict__ b1,
    const float* __restrict__ W2, const float* __restrict__ b2,
    const float* __restrict__ W3, const float* __restrict__ b3)
{
    __shared__ __align__(16) char smem[SMEM_SZ];
    int tid = threadIdx.x, wid = tid >> 5, lane = tid & 31;
    int gq = lane >> 2, t = lane & 3;
    int wbase = wid * 16;           // 8 warps x 16 rows

    for (int i = tid; i < 3072; i += 256){
        int ln = i & 31, ks = (i >> 5) & 3, n = (i >> 7) & 7, L = i >> 10;
        int g = ln >> 2, tt = ln & 3;
        int col = 8*n + g;
        int k0 = 16*ks + 2*tt;
        unsigned short h[4];
        #pragma unroll
        for (int j = 0; j < 4; j++){
            int kk = k0 + (j >> 1)*8 + (j & 1);
            float v;
            if (L == 0)      v = (kk < 54) ? __ldg(W0 + kk*64 + col) : 0.0f;
            else if (L == 1) v = __ldg(W1 + kk*64 + col);
            else             v = __ldg(W2 + kk*64 + col);
            h[j] = f2h(v);
        }
        *(uint2*)(smem + BF_OFF + i*8) = make_uint2(pack16(h[0],h[1]), pack16(h[2],h[3]));
    }
    for (int i = tid; i < 192; i += 256) *(float*)(smem + W3B_OFF + 4*i) = W3[i];
    if (tid < 32){
        *(uint32_t*)(smem + BIASH_OFF       + 4*tid) = packh2(b0[2*tid], b0[2*tid+1]);
        *(uint32_t*)(smem + BIASH_OFF + 128 + 4*tid) = packh2(b1[2*tid], b1[2*tid+1]);
    }
    if (tid < 64) *(float*)(smem + BIAS2_OFF + 4*tid) = b2[tid];
    if (tid < 3)  *(float*)(smem + B3_OFF + 4*tid) = b3[tid];
    __syncthreads();

    int cnt    = g_count;
    int ntiles = (cnt + 127) >> 7;
    const uint32_t* fwp = (const uint32_t*)g_featr;

    for (int tile = blockIdx.x; tile < ntiles; tile += gridDim.x){
        int tbase = tile << 7;

        // A fragments: one m16 slice per warp (rows wbase..wbase+15)
        uint32_t ah[4][4];
        {
            int r0 = (tbase + wbase + gq) * 32;
            int r1 = r0 + 8*32;
            #pragma unroll
            for (int ks = 0; ks < 4; ks++){
                ah[ks][0] = __ldg(fwp + r0 + 8*ks + t);
                ah[ks][1] = __ldg(fwp + r1 + 8*ks + t);
                ah[ks][2] = __ldg(fwp + r0 + 8*ks + t + 4);
                ah[ks][3] = __ldg(fwp + r1 + 8*ks + t + 4);
            }
        }

        // layers 0,1: fp16 accumulation
        #pragma unroll 1
        for (int L = 0; L < 2; L++){
            uint32_t acch[8][2];
            #pragma unroll
            for (int n = 0; n < 8; n++){ acch[n][0] = 0u; acch[n][1] = 0u; }

            #pragma unroll
            for (int ks = 0; ks < 4; ks++){
                uint2 B[8];
                #pragma unroll
                for (int n = 0; n < 8; n++)
                    B[n] = *(uint2*)(smem + BF_OFF + ((((L*8 + n)*4 + ks)*32 + lane)*8));
                #pragma unroll
                for (int n = 0; n < 8; n++)
                    mma_fp16h(acch[n], ah[ks][0], ah[ks][1], ah[ks][2], ah[ks][3], B[n].x, B[n].y);
            }
            const uint32_t* bh = (const uint32_t*)(smem + BIASH_OFF + L*128);
            __half2 z = __floats2half2_rn(0.0f, 0.0f);
            #pragma unroll
            for (int n = 0; n < 8; n++){
                __half2 bb = *(__half2*)&bh[4*n + t];
                __half2 v0 = __hmax2(__hadd2(*(__half2*)&acch[n][0], bb), z);
                __half2 v1 = __hmax2(__hadd2(*(__half2*)&acch[n][1], bb), z);
                int ks2 = n >> 1, w = (n & 1)*2;
                ah[ks2][w]   = *(uint32_t*)&v0;
                ah[ks2][w+1] = *(uint32_t*)&v1;
            }
        }

        // layer 2: fp32 accumulation
        float acc[8][4];
        #pragma unroll
        for (int n = 0; n < 8; n++)
            #pragma unroll
            for (int j = 0; j < 4; j++) acc[n][j] = 0.0f;

        #pragma unroll
        for (int ks = 0; ks < 4; ks++){
            uint2 B[8];
            #pragma unroll
            for (int n = 0; n < 8; n++)
                B[n] = *(uint2*)(smem + BF_OFF + ((((2*8 + n)*4 + ks)*32 + lane)*8));
            #pragma unroll
            for (int n = 0; n < 8; n++)
                mma_fp16(acc[n], ah[ks][0], ah[ks][1], ah[ks][2], ah[ks][3], B[n].x, B[n].y);
        }

        float rgbq[2][3];
        {
            const float* w3 = (const float*)(smem + W3B_OFF);
            #pragma unroll
            for (int sl = 0; sl < 2; sl++){ rgbq[sl][0]=0.f; rgbq[sl][1]=0.f; rgbq[sl][2]=0.f; }
            #pragma unroll
            for (int n = 0; n < 8; n++){
                int col0 = n*8 + 2*t;
                float2 bb = *(float2*)(smem + BIAS2_OFF + col0*4);
                float v0 = fmaxf(acc[n][0] + bb.x, 0.0f);
                float v1 = fmaxf(acc[n][1] + bb.y, 0.0f);
                float v2 = fmaxf(acc[n][2] + bb.x, 0.0f);
                float v3 = fmaxf(acc[n][3] + bb.y, 0.0f);
                #pragma unroll
                for (int c = 0; c < 3; c++){
                    rgbq[0][c] += v0*w3[col0*3+c] + v1*w3[(col0+1)*3+c];
                    rgbq[1][c] += v2*w3[col0*3+c] + v3*w3[(col0+1)*3+c];
                }
            }
        }

        #pragma unroll
        for (int sl = 0; sl < 2; sl++)
            #pragma unroll
            for (int c = 0; c < 3; c++){
                float v = rgbq[sl][c];
                v += __shfl_xor_sync(0xffffffffu, v, 1);
                v += __shfl_xor_sync(0xffffffffu, v, 2);
                rgbq[sl][c] = v;
            }
        if (t == 0){
            const float* bb3 = (const float*)(smem + B3_OFF);
            #pragma unroll
            for (int h = 0; h < 2; h++){
                int gi = tbase + wbase + gq + 8*h;
                if (gi < cnt){
                    int sidx = g_sidx[gi];
                    g_rgb[sidx]        = 1.0f/(1.0f + __expf(-(rgbq[h][0] + bb3[0])));
                    g_rgb[NTOT+sidx]   = 1.0f/(1.0f + __expf(-(rgbq[h][1] + bb3[1])));
                    g_rgb[2*NTOT+sidx] = 1.0f/(1.0f + __expf(-(rgbq[h][2] + bb3[2])));
                }
            }
        }
    }
}

// ---------------- kernel 3: warp-per-ray composite (parallel chunk scans) ----
__global__ __launch_bounds__(128) void k_perray(float* __restrict__ out)
{
    int gtid = blockIdx.x * 128 + threadIdx.x;
    if (gtid == 0) g_count = 0;  // reset for next replay
    int r    = gtid >> 5;
    int lane = threadIdx.x & 31;

    float *o_rgb   = out;
    float *o_depth = out + 12288;
    float *o_disp  = out + 16384;
    float *o_acc   = out + 20480;
    float *o_nrm   = out + 24576;
    float *o_w     = out + 36864;
    float *o_ai    = out + 1085440;

    int base = r << 8;

    float alp[8], v[8];
    #pragma unroll
    for (int c = 0; c < 8; c++) alp[c] = g_alpha[base + c*32 + lane];
    #pragma unroll
    for (int c = 0; c < 8; c++) v[c] = fmaxf(1.0f - alp[c], 1e-10f);

    #pragma unroll
    for (int off = 1; off < 32; off <<= 1){
        float o[8];
        #pragma unroll
        for (int c = 0; c < 8; c++) o[c] = __shfl_up_sync(0xffffffffu, v[c], off);
        #pragma unroll
        for (int c = 0; c < 8; c++) if (lane >= off) v[c] *= o[c];
    }

    float tot[8], Pc[8];
    #pragma unroll
    for (int c = 0; c < 8; c++) tot[c] = __shfl_sync(0xffffffffu, v[c], 31);
    float P = 1.0f;
    #pragma unroll
    for (int c = 0; c < 8; c++){ Pc[c] = P; P *= tot[c]; }

    float pv[8], w[8];
    #pragma unroll
    for (int c = 0; c < 8; c++) pv[c] = __shfl_up_sync(0xffffffffu, v[c], 1);
    #pragma unroll
    for (int c = 0; c < 8; c++){
        float excl = lane ? Pc[c]*pv[c] : Pc[c];
        w[c] = alp[c]*excl;
        int idx = base + c*32 + lane;
        o_w[idx]                    = w[c];
        o_ai[r*257 + 1 + c*32+lane] = Pc[c]*v[c];
    }

    float sr0=0.f, sr1=0.f, sr2=0.f, sd=0.f, sa=0.f, sn0=0.f, sn1=0.f, sn2=0.f;
    #pragma unroll
    for (int c = 0; c < 8; c++){
        int idx = base + c*32 + lane;
        float t = T0 + (float)(c*32+lane) * DT;
        sd  += w[c]*t;  sa += w[c];
        sr0 += w[c]*g_rgb[idx]; sr1 += w[c]*g_rgb[NTOT+idx]; sr2 += w[c]*g_rgb[2*NTOT+idx];
        sn0 += w[c]*g_nrm[idx]; sn1 += w[c]*g_nrm[NTOT+idx]; sn2 += w[c]*g_nrm[2*NTOT+idx];
    }
    #pragma unroll
    for (int off = 16; off; off >>= 1){
        sr0 += __shfl_xor_sync(0xffffffffu, sr0, off);
        sr1 += __shfl_xor_sync(0xffffffffu, sr1, off);
        sr2 += __shfl_xor_sync(0xffffffffu, sr2, off);
        sd  += __shfl_xor_sync(0xffffffffu, sd,  off);
        sa  += __shfl_xor_sync(0xffffffffu, sa,  off);
        sn0 += __shfl_xor_sync(0xffffffffu, sn0, off);
        sn1 += __shfl_xor_sync(0xffffffffu, sn1, off);
        sn2 += __shfl_xor_sync(0xffffffffu, sn2, off);
    }
    if (lane == 0){
        o_rgb[r*3]   = sr0 + P;
        o_rgb[r*3+1] = sr1 + P;
        o_rgb[r*3+2] = sr2 + P;
        float dm = sd + P * 3.0f;
        o_depth[r] = dm;
        o_disp[r]  = 1.0f / dm;
        o_acc[r]   = sa;
        o_nrm[r*3]   = sn0;
        o_nrm[r*3+1] = sn1;
        o_nrm[r*3+2] = sn2;
        o_ai[r*257]  = 1.0f;
    }
}

extern "C" void kernel_launch(void* const* d_in, const int* in_sizes, int n_in,
                              void* d_out, int out_size)
{
    const float* rays_o   = (const float*)d_in[0];
    const float* rays_d   = (const float*)d_in[1];
    const float* viewdirs = (const float*)d_in[2];
    const float* lat_grid = (const float*)d_in[3];
    const float* nrm_grid = (const float*)d_in[4];
    const float* W0 = (const float*)d_in[5];
    const float* b0 = (const float*)d_in[6];
    const float* W1 = (const float*)d_in[7];
    const float* b1 = (const float*)d_in[8];
    const float* W2 = (const float*)d_in[9];
    const float* b2 = (const float*)d_in[10];
    const float* W3 = (const float*)d_in[11];
    const float* b3 = (const float*)d_in[12];

    k_xpose<<<RES3/512, 256>>>(lat_grid, nrm_grid);
    k_feat<<<NTOT/128, 128>>>(rays_o, rays_d, viewdirs);
    k_mlp<<<444, 256>>>(W0, b0, W1, b1, W2, b2, W3, b3);
    k_perray<<<NRAYS*32/128, 128>>>((float*)d_out);
}

// round 15
// speedup vs baseline: 1.3524x; 1.3524x over previous
#include <cuda_runtime.h>
#include <cuda_fp16.h>
#include <math.h>
#include <stdint.h>

#define NRAYS 4096
#define NSAMP 256
#define NTOT  (NRAYS*NSAMP)
#define STRIDE (NTOT + 128)
#define RES   128
#define RES3  (RES*RES*RES)
#define T0    0.2f
#define DT    (2.8f/255.0f)
#define ACT_SHIFT (-4.595119850134589f)

// ---------------- scratch ----------------------------------------------------
__device__ float    g_alpha[NTOT];
__device__ float    g_rgb[3*NTOT];
__device__ float    g_nrm[3*NTOT];
__device__ uint4    g_lat4[2*RES3];     // 16 fp16 latent channels per voxel
__device__ uint2    g_nrm2[RES3];       // nx,ny,nz fp16 + pad
__device__ uint4    g_featr[STRIDE*8];  // row-major: 64 fp16 features per sample
__device__ int      g_sidx[STRIDE];
__device__ int      g_count;

// ---------------- helpers ----------------------------------------------------
__device__ __forceinline__ uint32_t pack16(unsigned short lo, unsigned short hi){
    return (uint32_t)lo | ((uint32_t)hi << 16);
}
__device__ __forceinline__ unsigned short f2h(float v){
    return __half_as_ushort(__float2half_rn(v));
}
__device__ __forceinline__ uint32_t packh2(float a, float b){
    __half2 h = __floats2half2_rn(a, b);
    return *(uint32_t*)&h;
}
__device__ __forceinline__ float2 h2f(uint32_t u){
    __half2 h = *reinterpret_cast<__half2*>(&u);
    return __half22float2(h);
}
__device__ __forceinline__ void mma_fp16(float* d, uint32_t a0, uint32_t a1,
                                         uint32_t a2, uint32_t a3,
                                         uint32_t b0, uint32_t b1){
    asm volatile(
        "mma.sync.aligned.m16n8k16.row.col.f32.f16.f16.f32 "
        "{%0,%1,%2,%3}, {%4,%5,%6,%7}, {%8,%9}, {%0,%1,%2,%3};"
        : "+f"(d[0]), "+f"(d[1]), "+f"(d[2]), "+f"(d[3])
        : "r"(a0), "r"(a1), "r"(a2), "r"(a3), "r"(b0), "r"(b1));
}
__device__ __forceinline__ void mma_fp16h(uint32_t* d, uint32_t a0, uint32_t a1,
                                          uint32_t a2, uint32_t a3,
                                          uint32_t b0, uint32_t b1){
    asm volatile(
        "mma.sync.aligned.m16n8k16.row.col.f16.f16.f16.f16 "
        "{%0,%1}, {%2,%3,%4,%5}, {%6,%7}, {%0,%1};"
        : "+r"(d[0]), "+r"(d[1])
        : "r"(a0), "r"(a1), "r"(a2), "r"(a3), "r"(b0), "r"(b1));
}

// ---------------- kernel 0: grid transpose (2 voxels/thread, float2 reads) ---
__global__ __launch_bounds__(256) void k_xpose(
    const float* __restrict__ lat, const float* __restrict__ nrm)
{
    int v2 = blockIdx.x * 256 + threadIdx.x;
    unsigned short ha[16], hb[16];
    #pragma unroll
    for (int c = 0; c < 16; c++){
        float2 f = __ldg((const float2*)(lat + c*RES3) + v2);
        ha[c] = f2h(f.x); hb[c] = f2h(f.y);
    }
    uint4 w0, w1, w2, w3;
    w0.x = pack16(ha[0],ha[1]);   w0.y = pack16(ha[2],ha[3]);
    w0.z = pack16(ha[4],ha[5]);   w0.w = pack16(ha[6],ha[7]);
    w1.x = pack16(ha[8],ha[9]);   w1.y = pack16(ha[10],ha[11]);
    w1.z = pack16(ha[12],ha[13]); w1.w = pack16(ha[14],ha[15]);
    w2.x = pack16(hb[0],hb[1]);   w2.y = pack16(hb[2],hb[3]);
    w2.z = pack16(hb[4],hb[5]);   w2.w = pack16(hb[6],hb[7]);
    w3.x = pack16(hb[8],hb[9]);   w3.y = pack16(hb[10],hb[11]);
    w3.z = pack16(hb[12],hb[13]); w3.w = pack16(hb[14],hb[15]);
    g_lat4[4*v2]   = w0;
    g_lat4[4*v2+1] = w1;
    g_lat4[4*v2+2] = w2;
    g_lat4[4*v2+3] = w3;
    float2 n0 = __ldg((const float2*)(nrm)            + v2);
    float2 n1 = __ldg((const float2*)(nrm +   RES3)   + v2);
    float2 n2 = __ldg((const float2*)(nrm + 2*RES3)   + v2);
    uint4 nq;
    nq.x = pack16(f2h(n0.x), f2h(n1.x));
    nq.y = pack16(f2h(n2.x), 0);
    nq.z = pack16(f2h(n0.y), f2h(n1.y));
    nq.w = pack16(f2h(n2.y), 0);
    ((uint4*)g_nrm2)[v2] = nq;
}

// ---------------- kernel 1: featurize + compact ------------------------------
__global__ __launch_bounds__(256) void k_feat(
    const float* __restrict__ rays_o, const float* __restrict__ rays_d,
    const float* __restrict__ viewdirs)
{
    int idx  = blockIdx.x * 256 + threadIdx.x;
    int r    = idx >> 8, s = idx & 255;
    int lane = threadIdx.x & 31;

    float ox = rays_o[r*3], oy = rays_o[r*3+1], oz = rays_o[r*3+2];
    float dx = rays_d[r*3], dy = rays_d[r*3+1], dz = rays_d[r*3+2];
    float dinv = rsqrtf(dx*dx + dy*dy + dz*dz);
    dx *= dinv; dy *= dinv; dz *= dinv;

    float t  = T0 + (float)s * DT;
    float px = ox + dx*t, py = oy + dy*t, pz = oz + dz*t;

    bool inb = (px >= -1.0f) & (px <= 1.0f) & (py >= -1.0f) & (py <= 1.0f)
             & (pz >= -1.0f) & (pz <= 1.0f);

    unsigned mask = __ballot_sync(0xffffffffu, inb);
    int base = 0;
    if (mask){
        if (lane == 0) base = atomicAdd(&g_count, __popc(mask));
        base = __shfl_sync(0xffffffffu, base, 0);
    }
    if (!inb){ g_alpha[idx] = 0.0f; return; }
    int pos = base + __popc(mask & ((1u << lane) - 1u));
    g_sidx[pos] = idx;

    float ux = fminf(fmaxf((px + 1.0f) * 0.5f, 0.0f), 1.0f) * 127.0f;
    float uy = fminf(fmaxf((py + 1.0f) * 0.5f, 0.0f), 1.0f) * 127.0f;
    float uz = fminf(fmaxf((pz + 1.0f) * 0.5f, 0.0f), 1.0f) * 127.0f;
    int x0 = min((int)floorf(ux), 126);
    int y0 = min((int)floorf(uy), 126);
    int z0 = min((int)floorf(uz), 126);
    float fx = ux - (float)x0, fy = uy - (float)y0, fz = uz - (float)z0;
    float gx = 1.0f - fx, gy = 1.0f - fy, gz = 1.0f - fz;

    int o000 = (x0*RES + y0)*RES + z0;
    int offs[8] = { o000, o000+1, o000+RES, o000+RES+1,
                    o000+RES*RES, o000+RES*RES+1, o000+RES*RES+RES, o000+RES*RES+RES+1 };
    float ws[8] = { gx*gy*gz, gx*gy*fz, gx*fy*gz, gx*fy*fz,
                    fx*gy*gz, fx*gy*fz, fx*fy*gz, fx*fy*fz };

    float L[16]; float N3[3];
    #pragma unroll
    for (int c = 0; c < 16; c++) L[c] = 0.0f;
    N3[0] = N3[1] = N3[2] = 0.0f;

    #pragma unroll
    for (int c = 0; c < 8; c++){
        int o = offs[c];
        float w = ws[c];
        uint4 pa = __ldg(&g_lat4[2*o]);
        uint4 pb = __ldg(&g_lat4[2*o+1]);
        uint2 pn = __ldg(&g_nrm2[o]);
        float2 f;
        f = h2f(pa.x); L[0]  += w*f.x; L[1]  += w*f.y;
        f = h2f(pa.y); L[2]  += w*f.x; L[3]  += w*f.y;
        f = h2f(pa.z); L[4]  += w*f.x; L[5]  += w*f.y;
        f = h2f(pa.w); L[6]  += w*f.x; L[7]  += w*f.y;
        f = h2f(pb.x); L[8]  += w*f.x; L[9]  += w*f.y;
        f = h2f(pb.y); L[10] += w*f.x; L[11] += w*f.y;
        f = h2f(pb.z); L[12] += w*f.x; L[13] += w*f.y;
        f = h2f(pb.w); L[14] += w*f.x; L[15] += w*f.y;
        f = h2f(pn.x); N3[0] += w*f.x; N3[1] += w*f.y;
        f = h2f(pn.y); N3[2] += w*f.x;
    }

    float nx = N3[0], ny = N3[1], nz = N3[2];
    float nl = sqrtf(nx*nx + ny*ny + nz*nz);
    float ninv = 1.0f / fmaxf(nl, 1e-12f);
    nx *= ninv; ny *= ninv; nz *= ninv;

    float d0 = L[0] + ACT_SHIFT;
    float sp = fmaxf(d0, 0.0f) + log1pf(__expf(-fabsf(d0)));
    g_alpha[idx] = 1.0f - __expf(-sp * 0.5f);
    g_nrm[idx] = nx; g_nrm[NTOT+idx] = ny; g_nrm[2*NTOT+idx] = nz;

    float vx = viewdirs[r*3], vy = viewdirs[r*3+1], vz = viewdirs[r*3+2];
    float vinv = rsqrtf(vx*vx + vy*vy + vz*vz);
    vx *= vinv; vy *= vinv; vz *= vinv;
    float dot = -(vx*nx + vy*ny + vz*nz);
    float rdx = 2.0f*dot*nx + vx, rdy = 2.0f*dot*ny + vy, rdz = 2.0f*dot*nz + vz;

    float fv[54];
    #pragma unroll
    for (int c = 0; c < 15; c++) fv[c] = L[c+1];
    fv[15] = rdx; fv[16] = rdy; fv[17] = rdz;
    float fq = 1.0f;
    #pragma unroll
    for (int k = 0; k < 6; k++){
        float sx, cx, sy, cy, sz, cz;
        __sincosf(fq*rdx, &sx, &cx);
        __sincosf(fq*rdy, &sy, &cy);
        __sincosf(fq*rdz, &sz, &cz);
        fv[18+3*k] = sx; fv[18+3*k+1] = sy; fv[18+3*k+2] = sz;
        fv[36+3*k] = cx; fv[36+3*k+1] = cy; fv[36+3*k+2] = cz;
        fq *= 2.0f;
    }
    uint32_t fw[32];
    #pragma unroll
    for (int w = 0; w < 27; w++) fw[w] = packh2(fv[2*w], fv[2*w+1]);
    #pragma unroll
    for (int w = 27; w < 32; w++) fw[w] = 0;
    uint4* dst = g_featr + pos*8;
    #pragma unroll
    for (int i = 0; i < 8; i++)
        dst[i] = make_uint4(fw[4*i], fw[4*i+1], fw[4*i+2], fw[4*i+3]);
}

// ---------------- kernel 2: HMMA MLP, f16-acc L0/L1, f32-acc L2 --------------
#define BF_OFF    0          // B frags: 3*8*4*32*8 = 24576
#define BIASH_OFF 24576      // b0,b1 as half2: 2*128 = 256
#define BIAS2_OFF 24832      // b2 f32: 256
#define W3B_OFF   25088      // 192*4 = 768
#define B3_OFF    25856      // 16
#define SMEM_SZ   25872

__global__ __launch_bounds__(128) void k_mlp(
    const float* __restrict__ W0, const float* __restrict__ b0,
    const float* __restrict__ W1, const float* __restrict__ b1,
    const float* __restrict__ W2, const float* __restrict__ b2,
    const float* __restrict__ W3, const float* __restrict__ b3)
{
    __shared__ __align__(16) char smem[SMEM_SZ];
    int tid = threadIdx.x, wid = tid >> 5, lane = tid & 31;
    int gq = lane >> 2, t = lane & 3;
    int wbase = wid * 32;

    for (int i = tid; i < 3072; i += 128){
        int ln = i & 31, ks = (i >> 5) & 3, n = (i >> 7) & 7, L = i >> 10;
        int g = ln >> 2, tt = ln & 3;
        int col = 8*n + g;
        int k0 = 16*ks + 2*tt;
        unsigned short h[4];
        #pragma unroll
        for (int j = 0; j < 4; j++){
            int kk = k0 + (j >> 1)*8 + (j & 1);
            float v;
            if (L == 0)      v = (kk < 54) ? __ldg(W0 + kk*64 + col) : 0.0f;
            else if (L == 1) v = __ldg(W1 + kk*64 + col);
            else             v = __ldg(W2 + kk*64 + col);
            h[j] = f2h(v);
        }
        *(uint2*)(smem + BF_OFF + i*8) = make_uint2(pack16(h[0],h[1]), pack16(h[2],h[3]));
    }
    for (int i = tid; i < 192; i += 128) *(float*)(smem + W3B_OFF + 4*i) = W3[i];
    if (tid < 32){
        *(uint32_t*)(smem + BIASH_OFF       + 4*tid) = packh2(b0[2*tid], b0[2*tid+1]);
        *(uint32_t*)(smem + BIASH_OFF + 128 + 4*tid) = packh2(b1[2*tid], b1[2*tid+1]);
    }
    if (tid < 64) *(float*)(smem + BIAS2_OFF + 4*tid) = b2[tid];
    if (tid < 3)  *(float*)(smem + B3_OFF + 4*tid) = b3[tid];
    __syncthreads();

    int cnt    = g_count;
    int ntiles = (cnt + 127) >> 7;
    const uint32_t* fwp = (const uint32_t*)g_featr;

    for (int tile = blockIdx.x; tile < ntiles; tile += gridDim.x){
        int tbase = tile << 7;

        uint32_t ah[2][4][4];
        #pragma unroll
        for (int m = 0; m < 2; m++){
            int r0 = (tbase + wbase + 16*m + gq) * 32;
            int r1 = r0 + 8*32;
            #pragma unroll
            for (int ks = 0; ks < 4; ks++){
                ah[m][ks][0] = __ldg(fwp + r0 + 8*ks + t);
                ah[m][ks][1] = __ldg(fwp + r1 + 8*ks + t);
                ah[m][ks][2] = __ldg(fwp + r0 + 8*ks + t + 4);
                ah[m][ks][3] = __ldg(fwp + r1 + 8*ks + t + 4);
            }
        }

        // layers 0,1: fp16 accumulation
        #pragma unroll 1
        for (int L = 0; L < 2; L++){
            uint32_t acch[2][8][2];
            #pragma unroll
            for (int m = 0; m < 2; m++)
                #pragma unroll
                for (int n = 0; n < 8; n++){ acch[m][n][0] = 0u; acch[m][n][1] = 0u; }

            #pragma unroll
            for (int ks = 0; ks < 4; ks++){
                uint2 B[8];
                #pragma unroll
                for (int n = 0; n < 8; n++)
                    B[n] = *(uint2*)(smem + BF_OFF + ((((L*8 + n)*4 + ks)*32 + lane)*8));
                #pragma unroll
                for (int n = 0; n < 8; n++){
                    mma_fp16h(acch[0][n], ah[0][ks][0], ah[0][ks][1], ah[0][ks][2], ah[0][ks][3], B[n].x, B[n].y);
                    mma_fp16h(acch[1][n], ah[1][ks][0], ah[1][ks][1], ah[1][ks][2], ah[1][ks][3], B[n].x, B[n].y);
                }
            }
            const uint32_t* bh = (const uint32_t*)(smem + BIASH_OFF + L*128);
            __half2 z = __floats2half2_rn(0.0f, 0.0f);
            #pragma unroll
            for (int m = 0; m < 2; m++)
                #pragma unroll
                for (int n = 0; n < 8; n++){
                    __half2 bb = *(__half2*)&bh[4*n + t];
                    __half2 v0 = __hmax2(__hadd2(*(__half2*)&acch[m][n][0], bb), z);
                    __half2 v1 = __hmax2(__hadd2(*(__half2*)&acch[m][n][1], bb), z);
                    int ks2 = n >> 1, w = (n & 1)*2;
                    ah[m][ks2][w]   = *(uint32_t*)&v0;
                    ah[m][ks2][w+1] = *(uint32_t*)&v1;
                }
        }

        // layer 2: fp32 accumulation
        float acc[2][8][4];
        #pragma unroll
        for (int m = 0; m < 2; m++)
            #pragma unroll
            for (int n = 0; n < 8; n++)
                #pragma unroll
                for (int j = 0; j < 4; j++) acc[m][n][j] = 0.0f;

        #pragma unroll
        for (int ks = 0; ks < 4; ks++){
            uint2 B[8];
            #pragma unroll
            for (int n = 0; n < 8; n++)
                B[n] = *(uint2*)(smem + BF_OFF + ((((2*8 + n)*4 + ks)*32 + lane)*8));
            #pragma unroll
            for (int n = 0; n < 8; n++){
                mma_fp16(acc[0][n], ah[0][ks][0], ah[0][ks][1], ah[0][ks][2], ah[0][ks][3], B[n].x, B[n].y);
                mma_fp16(acc[1][n], ah[1][ks][0], ah[1][ks][1], ah[1][ks][2], ah[1][ks][3], B[n].x, B[n].y);
            }
        }

        float rgbq[4][3];
        {
            const float* w3 = (const float*)(smem + W3B_OFF);
            #pragma unroll
            for (int sl = 0; sl < 4; sl++){ rgbq[sl][0]=0.f; rgbq[sl][1]=0.f; rgbq[sl][2]=0.f; }
            #pragma unroll
            for (int m = 0; m < 2; m++)
                #pragma unroll
                for (int n = 0; n < 8; n++){
                    int col0 = n*8 + 2*t;
                    float2 bb = *(float2*)(smem + BIAS2_OFF + col0*4);
                    float v0 = fmaxf(acc[m][n][0] + bb.x, 0.0f);
                    float v1 = fmaxf(acc[m][n][1] + bb.y, 0.0f);
                    float v2 = fmaxf(acc[m][n][2] + bb.x, 0.0f);
                    float v3 = fmaxf(acc[m][n][3] + bb.y, 0.0f);
                    #pragma unroll
                    for (int c = 0; c < 3; c++){
                        rgbq[2*m  ][c] += v0*w3[col0*3+c] + v1*w3[(col0+1)*3+c];
                        rgbq[2*m+1][c] += v2*w3[col0*3+c] + v3*w3[(col0+1)*3+c];
                    }
                }
        }

        #pragma unroll
        for (int sl = 0; sl < 4; sl++)
            #pragma unroll
            for (int c = 0; c < 3; c++){
                float v = rgbq[sl][c];
                v += __shfl_xor_sync(0xffffffffu, v, 1);
                v += __shfl_xor_sync(0xffffffffu, v, 2);
                rgbq[sl][c] = v;
            }
        if (t == 0){
            const float* bb3 = (const float*)(smem + B3_OFF);
            #pragma unroll
            for (int sl = 0; sl < 4; sl++){
                int m = sl >> 1, h = sl & 1;
                int gi = tbase + wbase + m*16 + gq + 8*h;
                if (gi < cnt){
                    int sidx = g_sidx[gi];
                    g_rgb[sidx]        = 1.0f/(1.0f + __expf(-(rgbq[sl][0] + bb3[0])));
                    g_rgb[NTOT+sidx]   = 1.0f/(1.0f + __expf(-(rgbq[sl][1] + bb3[1])));
                    g_rgb[2*NTOT+sidx] = 1.0f/(1.0f + __expf(-(rgbq[sl][2] + bb3[2])));
                }
            }
        }
    }
}

// ---------------- kernel 3: warp-per-ray composite (parallel chunk scans) ----
__global__ __launch_bounds__(128) void k_perray(float* __restrict__ out)
{
    int gtid = blockIdx.x * 128 + threadIdx.x;
    if (gtid == 0) g_count = 0;  // reset for next replay
    int r    = gtid >> 5;
    int lane = threadIdx.x & 31;

    float *o_rgb   = out;
    float *o_depth = out + 12288;
    float *o_disp  = out + 16384;
    float *o_acc   = out + 20480;
    float *o_nrm   = out + 24576;
    float *o_w     = out + 36864;
    float *o_ai    = out + 1085440;

    int base = r << 8;

    float alp[8], v[8];
    #pragma unroll
    for (int c = 0; c < 8; c++) alp[c] = g_alpha[base + c*32 + lane];
    #pragma unroll
    for (int c = 0; c < 8; c++) v[c] = fmaxf(1.0f - alp[c], 1e-10f);

    #pragma unroll
    for (int off = 1; off < 32; off <<= 1){
        float o[8];
        #pragma unroll
        for (int c = 0; c < 8; c++) o[c] = __shfl_up_sync(0xffffffffu, v[c], off);
        #pragma unroll
        for (int c = 0; c < 8; c++) if (lane >= off) v[c] *= o[c];
    }

    float tot[8], Pc[8];
    #pragma unroll
    for (int c = 0; c < 8; c++) tot[c] = __shfl_sync(0xffffffffu, v[c], 31);
    float P = 1.0f;
    #pragma unroll
    for (int c = 0; c < 8; c++){ Pc[c] = P; P *= tot[c]; }

    float pv[8], w[8];
    #pragma unroll
    for (int c = 0; c < 8; c++) pv[c] = __shfl_up_sync(0xffffffffu, v[c], 1);
    #pragma unroll
    for (int c = 0; c < 8; c++){
        float excl = lane ? Pc[c]*pv[c] : Pc[c];
        w[c] = alp[c]*excl;
        int idx = base + c*32 + lane;
        o_w[idx]                    = w[c];
        o_ai[r*257 + 1 + c*32+lane] = Pc[c]*v[c];
    }

    float sr0=0.f, sr1=0.f, sr2=0.f, sd=0.f, sa=0.f, sn0=0.f, sn1=0.f, sn2=0.f;
    #pragma unroll
    for (int c = 0; c < 8; c++){
        int idx = base + c*32 + lane;
        float t = T0 + (float)(c*32+lane) * DT;
        sd  += w[c]*t;  sa += w[c];
        sr0 += w[c]*g_rgb[idx]; sr1 += w[c]*g_rgb[NTOT+idx]; sr2 += w[c]*g_rgb[2*NTOT+idx];
        sn0 += w[c]*g_nrm[idx]; sn1 += w[c]*g_nrm[NTOT+idx]; sn2 += w[c]*g_nrm[2*NTOT+idx];
    }
    #pragma unroll
    for (int off = 16; off; off >>= 1){
        sr0 += __shfl_xor_sync(0xffffffffu, sr0, off);
        sr1 += __shfl_xor_sync(0xffffffffu, sr1, off);
        sr2 += __shfl_xor_sync(0xffffffffu, sr2, off);
        sd  += __shfl_xor_sync(0xffffffffu, sd,  off);
        sa  += __shfl_xor_sync(0xffffffffu, sa,  off);
        sn0 += __shfl_xor_sync(0xffffffffu, sn0, off);
        sn1 += __shfl_xor_sync(0xffffffffu, sn1, off);
        sn2 += __shfl_xor_sync(0xffffffffu, sn2, off);
    }
    if (lane == 0){
        o_rgb[r*3]   = sr0 + P;
        o_rgb[r*3+1] = sr1 + P;
        o_rgb[r*3+2] = sr2 + P;
        float dm = sd + P * 3.0f;
        o_depth[r] = dm;
        o_disp[r]  = 1.0f / dm;
        o_acc[r]   = sa;
        o_nrm[r*3]   = sn0;
        o_nrm[r*3+1] = sn1;
        o_nrm[r*3+2] = sn2;
        o_ai[r*257]  = 1.0f;
    }
}

extern "C" void kernel_launch(void* const* d_in, const int* in_sizes, int n_in,
                              void* d_out, int out_size)
{
    const float* rays_o   = (const float*)d_in[0];
    const float* rays_d   = (const float*)d_in[1];
    const float* viewdirs = (const float*)d_in[2];
    const float* lat_grid = (const float*)d_in[3];
    const float* nrm_grid = (const float*)d_in[4];
    const float* W0 = (const float*)d_in[5];
    const float* b0 = (const float*)d_in[6];
    const float* W1 = (const float*)d_in[7];
    const float* b1 = (const float*)d_in[8];
    const float* W2 = (const float*)d_in[9];
    const float* b2 = (const float*)d_in[10];
    const float* W3 = (const float*)d_in[11];
    const float* b3 = (const float*)d_in[12];

    k_xpose<<<RES3/512, 256>>>(lat_grid, nrm_grid);
    k_feat<<<NTOT/256, 256>>>(rays_o, rays_d, viewdirs);
    k_mlp<<<592, 128>>>(W0, b0, W1, b1, W2, b2, W3, b3);
    k_perray<<<NRAYS*32/128, 128>>>((float*)d_out);
}